// round 2
// baseline (speedup 1.0000x reference)
#include <cuda_runtime.h>
#include <mma.h>
#include <cstdint>
#include <cstddef>

using namespace nvcuda;

// Problem dims (fixed by the dataset)
#define B_ROWS 65536
#define C_DIM  512
#define K_DIM  512

// ---------------- GEMM tiling ----------------
constexpr int BM = 128;          // block tile M
constexpr int BN = 64;           // block tile N
constexpr int BK = 32;           // block tile K
constexpr int PAD = 4;
constexpr int LDS_A = BK + PAD;  // 36 (multiple of 4 -> valid wmma ldm)
constexpr int A_FLOATS = BM * LDS_A;             // 4608
constexpr int B_BASE   = A_FLOATS;               // Bs starts after As
constexpr int B_FLOATS = BN * LDS_A;             // 2304
constexpr int LDC = BN + 4;                      // 68
constexpr int CS_FLOATS = BM * LDC;              // 8704 (overlaps As+Bs region, used after sync)
constexpr int AUX_BASE = CS_FLOATS;              // 8704: bias[64], wag0[64], wag1[64]
constexpr int SMEM_FLOATS = AUX_BASE + 3 * BN;   // 8896 floats = 35584 B (< 48KB static)

// ---------------- EMA scan config ----------------
constexpr int EMA_CHUNK  = 128;   // outputs per worker
constexpr int EMA_WARMUP = 512;   // 0.95^512 ~ 4e-12 << fp32 ulp -> bitwise-safe truncation

// ============================================================
// Kernel 1: init wager output with bias (atomics accumulate onto it)
// ============================================================
__global__ void init_wager_kernel(float* __restrict__ wager,
                                  const float* __restrict__ b_wager)
{
    int i = blockIdx.x * blockDim.x + threadIdx.x;
    if (i < B_ROWS) {
        float2 v = make_float2(b_wager[0], b_wager[1]);
        reinterpret_cast<float2*>(wager)[i] = v;
    }
}

// ============================================================
// Kernel 2: EMA target. ema_i = 0.05*g_i + 0.95*ema_{i-1}; greater = g_i > ema_i
// Parallel via warmup truncation (geometric decay kills the carry dependency).
// ============================================================
__global__ void ema_target_kernel(const float* __restrict__ rewards,
                                  float* __restrict__ target)
{
    int t = blockIdx.x * blockDim.x + threadIdx.x;   // 512 workers
    int start = t * EMA_CHUNK;
    if (start >= B_ROWS) return;
    int w0 = start - EMA_WARMUP;
    if (w0 < 0) w0 = 0;

    float ema = 0.0f;
    for (int i = w0; i < start; i++) {
        ema = 0.05f * rewards[i] + 0.95f * ema;
    }
    for (int i = start; i < start + EMA_CHUNK; i++) {
        float g = rewards[i];
        ema = 0.05f * g + 0.95f * ema;
        bool gt = g > ema;
        target[2 * i + 0] = gt ? 1.0f : 0.0f;
        target[2 * i + 1] = gt ? 0.0f : 1.0f;
    }
}

// ============================================================
// Kernel 3: fused tf32 GEMM + relu + cascade blend + wager GEMV
//   h        = relu(A @ W^T + b_comp)                 [BM x BN tile]
//   comp_out = r*h + (1-r)*prev                       (written)
//   wager   += comp_out-tile @ W_wager^T              (shuffle-reduce + atomicAdd)
// Block: 256 threads = 8 warps in a 4(M) x 2(N) grid; warp tile 32x32
// via 2x2 wmma 16x16x8 tf32 fragments.
// ============================================================
__global__ __launch_bounds__(256)
void gemm_fused_kernel(const float* __restrict__ A,
                       const float* __restrict__ prev,
                       const float* __restrict__ cascade,
                       const float* __restrict__ W,
                       const float* __restrict__ bias,
                       const float* __restrict__ Wwag,
                       float* __restrict__ wager,
                       float* __restrict__ comp)
{
    __shared__ float smem[SMEM_FLOATS];

    const int t  = threadIdx.x;
    const int n0 = blockIdx.x * BN;   // n-blocks fastest -> A slice shared in L2
    const int m0 = blockIdx.y * BM;

    // Cache bias and wager weights for this n-slab (used only in epilogue,
    // stored above the Cs region so they survive).
    if (t < BN) {
        smem[AUX_BASE + t]            = bias[n0 + t];
        smem[AUX_BASE + BN + t]       = Wwag[n0 + t];            // row 0 of W_wager [2,C]
        smem[AUX_BASE + 2 * BN + t]   = Wwag[C_DIM + n0 + t];    // row 1
    }

    // -------- staging layout --------
    const int lrow = t >> 3;   // 0..31
    const int lc4  = t & 7;    // 0..7 (float4 column)

    float4 aReg[4];
    float4 bReg[2];

    auto loadA = [&](int kt) {
#pragma unroll
        for (int p = 0; p < 4; p++) {
            int row = lrow + p * 32;
            aReg[p] = *reinterpret_cast<const float4*>(
                A + (size_t)(m0 + row) * K_DIM + kt * BK + lc4 * 4);
        }
    };
    auto loadB = [&](int kt) {
#pragma unroll
        for (int p = 0; p < 2; p++) {
            int row = lrow + p * 32;
            bReg[p] = *reinterpret_cast<const float4*>(
                W + (size_t)(n0 + row) * K_DIM + kt * BK + lc4 * 4);
        }
    };
    auto storeA = [&]() {
#pragma unroll
        for (int p = 0; p < 4; p++) {
            int row = lrow + p * 32;
            float* d = smem + row * LDS_A + lc4 * 4;
            d[0] = wmma::__float_to_tf32(aReg[p].x);
            d[1] = wmma::__float_to_tf32(aReg[p].y);
            d[2] = wmma::__float_to_tf32(aReg[p].z);
            d[3] = wmma::__float_to_tf32(aReg[p].w);
        }
    };
    auto storeB = [&]() {
#pragma unroll
        for (int p = 0; p < 2; p++) {
            int row = lrow + p * 32;
            float* d = smem + B_BASE + row * LDS_A + lc4 * 4;
            d[0] = wmma::__float_to_tf32(bReg[p].x);
            d[1] = wmma::__float_to_tf32(bReg[p].y);
            d[2] = wmma::__float_to_tf32(bReg[p].z);
            d[3] = wmma::__float_to_tf32(bReg[p].w);
        }
    };

    const int wid = t >> 5;
    const int wm  = wid & 3;    // 0..3 (M)
    const int wn  = wid >> 2;   // 0..1 (N)

    wmma::fragment<wmma::accumulator, 16, 16, 8, float> acc[2][2];
#pragma unroll
    for (int i = 0; i < 2; i++)
#pragma unroll
        for (int j = 0; j < 2; j++)
            wmma::fill_fragment(acc[i][j], 0.0f);

    // -------- mainloop (reg-staged, single smem buffer) --------
    constexpr int NT = K_DIM / BK;   // 16
    loadA(0); loadB(0);
    storeA(); storeB();
    __syncthreads();

    for (int kt = 0; kt < NT; kt++) {
        if (kt + 1 < NT) { loadA(kt + 1); loadB(kt + 1); }  // globals in flight over compute

#pragma unroll
        for (int kk = 0; kk < BK / 8; kk++) {
            wmma::fragment<wmma::matrix_a, 16, 16, 8, wmma::precision::tf32, wmma::row_major> af[2];
            wmma::fragment<wmma::matrix_b, 16, 16, 8, wmma::precision::tf32, wmma::col_major> bf[2];
#pragma unroll
            for (int i = 0; i < 2; i++)
                wmma::load_matrix_sync(af[i], smem + (wm * 32 + i * 16) * LDS_A + kk * 8, LDS_A);
#pragma unroll
            for (int j = 0; j < 2; j++)
                wmma::load_matrix_sync(bf[j], smem + B_BASE + (wn * 32 + j * 16) * LDS_A + kk * 8, LDS_A);
#pragma unroll
            for (int i = 0; i < 2; i++)
#pragma unroll
                for (int j = 0; j < 2; j++)
                    wmma::mma_sync(acc[i][j], af[i], bf[j], acc[i][j]);
        }
        __syncthreads();            // everyone done reading this k-slice
        if (kt + 1 < NT) {
            storeA(); storeB();
            __syncthreads();        // slice visible before next compute
        }
    }

    // -------- epilogue --------
    // Park accumulators in smem (reuses staging region; protected by final sync above).
    float* Cs = smem;
#pragma unroll
    for (int i = 0; i < 2; i++)
#pragma unroll
        for (int j = 0; j < 2; j++)
            wmma::store_matrix_sync(Cs + (wm * 32 + i * 16) * LDC + wn * 32 + j * 16,
                                    acc[i][j], LDC, wmma::mem_row_major);
    __syncthreads();

    const float r   = *cascade;
    const float omr = 1.0f - r;
    const int erow = t >> 4;        // 0..15
    const int ec   = (t & 15) * 4;  // 0,4,...,60

#pragma unroll
    for (int p = 0; p < 8; p++) {
        int row = erow + p * 16;
        int gm  = m0 + row;

        const float4 pv = *reinterpret_cast<const float4*>(
            prev + (size_t)gm * C_DIM + n0 + ec);

        float h0 = fmaxf(Cs[row * LDC + ec + 0] + smem[AUX_BASE + ec + 0], 0.0f);
        float h1 = fmaxf(Cs[row * LDC + ec + 1] + smem[AUX_BASE + ec + 1], 0.0f);
        float h2 = fmaxf(Cs[row * LDC + ec + 2] + smem[AUX_BASE + ec + 2], 0.0f);
        float h3 = fmaxf(Cs[row * LDC + ec + 3] + smem[AUX_BASE + ec + 3], 0.0f);

        float4 o;
        o.x = fmaf(r, h0, omr * pv.x);
        o.y = fmaf(r, h1, omr * pv.y);
        o.z = fmaf(r, h2, omr * pv.z);
        o.w = fmaf(r, h3, omr * pv.w);

        *reinterpret_cast<float4*>(comp + (size_t)gm * C_DIM + n0 + ec) = o;

        // partial wager for this row over 4 columns
        float w0 = o.x * smem[AUX_BASE + BN + ec + 0]
                 + o.y * smem[AUX_BASE + BN + ec + 1]
                 + o.z * smem[AUX_BASE + BN + ec + 2]
                 + o.w * smem[AUX_BASE + BN + ec + 3];
        float w1 = o.x * smem[AUX_BASE + 2 * BN + ec + 0]
                 + o.y * smem[AUX_BASE + 2 * BN + ec + 1]
                 + o.z * smem[AUX_BASE + 2 * BN + ec + 2]
                 + o.w * smem[AUX_BASE + 2 * BN + ec + 3];

        // reduce across the 16 lanes that own this row (stays within warp half)
#pragma unroll
        for (int off = 8; off; off >>= 1) {
            w0 += __shfl_xor_sync(0xffffffffu, w0, off);
            w1 += __shfl_xor_sync(0xffffffffu, w1, off);
        }
        if ((t & 15) == 0) {
            atomicAdd(wager + (size_t)gm * 2 + 0, w0);
            atomicAdd(wager + (size_t)gm * 2 + 1, w1);
        }
    }
}

// ============================================================
// Launch
// Inputs (metadata order):
//  0 comparison_matrix [B,512] f32   1 prev_comparison [B,512] f32
//  2 cascade_rate [1] f32            3 rewards [B] f32
//  4 W_comp [512,512] f32            5 b_comp [512] f32
//  6 W_wager [2,512] f32             7 b_wager [2] f32
// Output: concat( wager [B,2], comparison_out [B,512], target [B,2] ) f32
// ============================================================
extern "C" void kernel_launch(void* const* d_in, const int* in_sizes, int n_in,
                              void* d_out, int out_size)
{
    const float* A    = (const float*)d_in[0];
    const float* prev = (const float*)d_in[1];
    const float* casc = (const float*)d_in[2];
    const float* rew  = (const float*)d_in[3];
    const float* W    = (const float*)d_in[4];
    const float* bc   = (const float*)d_in[5];
    const float* Ww   = (const float*)d_in[6];
    const float* bw   = (const float*)d_in[7];

    float* out    = (float*)d_out;
    float* wager  = out;                                          // [B,2]
    float* comp   = out + (size_t)B_ROWS * 2;                     // [B,512]
    float* target = out + (size_t)B_ROWS * 2 + (size_t)B_ROWS * C_DIM;  // [B,2]

    // wager must be initialized (with bias) before GEMM atomics; stream order guarantees it.
    init_wager_kernel<<<(B_ROWS + 255) / 256, 256>>>(wager, bw);
    ema_target_kernel<<<4, 128>>>(rew, target);

    dim3 grid(C_DIM / BN, B_ROWS / BM);   // (8, 512); n fastest -> A slice L2 reuse
    gemm_fused_kernel<<<grid, 256>>>(A, prev, casc, W, bc, Ww, wager, comp);
}